// round 7
// baseline (speedup 1.0000x reference)
#include <cuda_runtime.h>
#include <cfloat>

#define BB 8
#define TT 2048
#define DD 512
#define KQ 32
#define TOPK 4
#define BT (BB*TT)
#define HID 1024
#define NCTA 128
#define DP (DD+4)
#define HP (HID+4)

__device__ float g_q[BT*KQ];
__device__ float g_kk[BT*KQ];
__device__ int   g_idx[BT*TOPK];
__device__ float g_gath[BT*DD];
__device__ float g_big[BT*HID];   // GEMM1 hidden, later reused for P
__device__ float g_ffn[BT*DD];
__device__ float g_y[BT*DD];
__device__ float g_hbuf[BB*HID];
__device__ float g_mem[BB*DD];
__device__ unsigned g_arr[NCTA*32];   // padded arrive flags (one 128B line each)

__device__ __forceinline__ float gelu_exact(float v) {
    return 0.5f * v * (1.0f + erff(v * 0.70710678118654752440f));
}
__device__ __forceinline__ unsigned ld_acq(const unsigned* p) {
    unsigned v; asm volatile("ld.acquire.gpu.u32 %0, [%1];" : "=r"(v) : "l"(p)); return v;
}
__device__ __forceinline__ void st_rel(unsigned* p, unsigned v) {
    asm volatile("st.release.gpu.u32 [%0], %1;" :: "l"(p), "r"(v));
}

__global__ void init_kernel() {
    int t = blockIdx.x * blockDim.x + threadIdx.x;
    if (t < BB*DD)   g_mem[t] = 0.0f;
    if (t < NCTA*32) g_arr[t] = 0u;
}

__global__ __launch_bounds__(128) void qk_kernel(
    const float* __restrict__ x, const float* __restrict__ Wq, const float* __restrict__ bq,
    const float* __restrict__ Wk, const float* __restrict__ bk)
{
    __shared__ float xs[4*DD];
    int r0 = blockIdx.x * 4, tid = threadIdx.x;
    for (int i = tid; i < 4*DD; i += 128) xs[i] = x[(size_t)r0*DD + i];
    __syncthreads();
    int r = tid >> 5, j = tid & 31;
    float sq = 0.f, sk = 0.f;
    const float* xr = &xs[r*DD];
    #pragma unroll 8
    for (int d = 0; d < DD; d++) {
        float xv = xr[d];
        sq += xv * Wq[d*KQ + j];
        sk += xv * Wk[d*KQ + j];
    }
    g_q [(size_t)(r0+r)*KQ + j] = sq + bq[j];
    g_kk[(size_t)(r0+r)*KQ + j] = sk + bk[j];
}

__global__ __launch_bounds__(256) void sim_topk_kernel() {
    __shared__ float ks[256*33];
    int b = blockIdx.x >> 8, t0 = (blockIdx.x & 255) * 8;
    int tid = threadIdx.x, warp = tid >> 5, lane = tid & 31;
    int t = t0 + warp;
    float qreg[KQ];
    #pragma unroll
    for (int i = 0; i < KQ; i++) qreg[i] = g_q[((size_t)b*TT + t)*KQ + i];
    float v0=-FLT_MAX,v1=-FLT_MAX,v2=-FLT_MAX,v3=-FLT_MAX;
    int   i0=0x7fffffff,i1=0x7fffffff,i2=0x7fffffff,i3=0x7fffffff;
    for (int c = 0; c < 8; c++) {
        int s0 = c * 256;
        __syncthreads();
        for (int i = tid; i < 256*KQ; i += 256) {
            int sl = i >> 5, kv = i & 31;
            ks[sl*33 + kv] = g_kk[((size_t)b*TT + s0 + sl)*KQ + kv];
        }
        __syncthreads();
        #pragma unroll
        for (int it = 0; it < 8; it++) {
            int sl = (it << 5) + lane;
            const float* kr = &ks[sl*33];
            float sim = 0.f;
            #pragma unroll
            for (int i = 0; i < KQ; i++) sim += qreg[i]*kr[i];
            int s = s0 + sl;
            if (sim > v3) {
                if (sim > v1) {
                    v3=v2;i3=i2; v2=v1;i2=i1;
                    if (sim > v0) { v1=v0;i1=i0; v0=sim;i0=s; }
                    else          { v1=sim;i1=s; }
                } else {
                    if (sim > v2) { v3=v2;i3=i2; v2=sim;i2=s; }
                    else          { v3=sim;i3=s; }
                }
            }
        }
    }
    for (int r = 0; r < 4; r++) {
        float bv = v0; int bi = i0;
        #pragma unroll
        for (int off = 16; off; off >>= 1) {
            float ov = __shfl_xor_sync(0xffffffffu, bv, off);
            int   oi = __shfl_xor_sync(0xffffffffu, bi, off);
            if (ov > bv || (ov == bv && oi < bi)) { bv = ov; bi = oi; }
        }
        if (i0 == bi) { v0=v1;i0=i1; v1=v2;i1=i2; v2=v3;i2=i3; v3=-FLT_MAX;i3=0x7fffffff; }
        if (lane == 0) g_idx[((size_t)b*TT + t)*TOPK + r] = bi;
    }
}

__global__ __launch_bounds__(128) void gather_kernel(const float* __restrict__ x) {
    int bt = blockIdx.x, b = bt >> 11;
    const int4 iv = *(const int4*)&g_idx[(size_t)bt*TOPK];
    const float4* xb = (const float4*)(x + (size_t)b*TT*DD);
    int d = threadIdx.x;
    float4 a = xb[(size_t)iv.x*(DD/4)+d], b4 = xb[(size_t)iv.y*(DD/4)+d];
    float4 c = xb[(size_t)iv.z*(DD/4)+d], e  = xb[(size_t)iv.w*(DD/4)+d];
    float4 m = {0.25f*(a.x+b4.x+c.x+e.x), 0.25f*(a.y+b4.y+c.y+e.y),
                0.25f*(a.z+b4.z+c.z+e.z), 0.25f*(a.w+b4.w+c.w+e.w)};
    ((float4*)(g_gath + (size_t)bt*DD))[d] = m;
}

// 128x128 tile, 8x8 micro, double-buffered. C = act(A @ B + bias).
// MODE 0: g_gath->g_big(gelu); 1: g_big->g_ffn; 2: g_y->g_big
template<int ACT, int MODE>
__global__ __launch_bounds__(256) void sgemm128(
    const float* __restrict__ Bmat, const float* __restrict__ bias, int N, int K)
{
    const float* A = (MODE==0) ? g_gath : (MODE==1) ? g_big : g_y;
    float*       C = (MODE==1) ? g_ffn  : g_big;
    __shared__ float As[2][8*128];
    __shared__ float Bs[2][8*128];
    int tid = threadIdx.x;
    int bm = blockIdx.y * 128, bn = blockIdx.x * 128;
    int tx = tid & 15, ty = tid >> 4;
    int ar = tid >> 1, ac = (tid & 1) << 2;
    int br = tid >> 5, bc = (tid & 31) << 2;
    const float* Ap = A + (size_t)(bm + ar)*K + ac;
    const float* Bp = Bmat + (size_t)br*N + bn + bc;
    float acc[8][8] = {};
    {
        float4 a4 = *(const float4*)Ap;
        float4 b4 = *(const float4*)Bp;
        As[0][(ac+0)*128 + ar] = a4.x;
        As[0][(ac+1)*128 + ar] = a4.y;
        As[0][(ac+2)*128 + ar] = a4.z;
        As[0][(ac+3)*128 + ar] = a4.w;
        *(float4*)&Bs[0][br*128 + bc] = b4;
    }
    __syncthreads();
    int cur = 0;
    for (int k0 = 0; k0 < K; k0 += 8) {
        float4 a4, b4;
        bool more = (k0 + 8) < K;
        if (more) {
            a4 = *(const float4*)(Ap + k0 + 8);
            b4 = *(const float4*)(Bp + (size_t)(k0 + 8)*N);
        }
        #pragma unroll
        for (int kk = 0; kk < 8; kk++) {
            float4 a0 = *(const float4*)&As[cur][kk*128 + ty*8];
            float4 a1 = *(const float4*)&As[cur][kk*128 + ty*8 + 4];
            float4 b0 = *(const float4*)&Bs[cur][kk*128 + tx*8];
            float4 b1 = *(const float4*)&Bs[cur][kk*128 + tx*8 + 4];
            float av[8] = {a0.x,a0.y,a0.z,a0.w,a1.x,a1.y,a1.z,a1.w};
            float bv[8] = {b0.x,b0.y,b0.z,b0.w,b1.x,b1.y,b1.z,b1.w};
            #pragma unroll
            for (int i = 0; i < 8; i++)
                #pragma unroll
                for (int j = 0; j < 8; j++) acc[i][j] += av[i]*bv[j];
        }
        if (more) {
            int nb = cur ^ 1;
            As[nb][(ac+0)*128 + ar] = a4.x;
            As[nb][(ac+1)*128 + ar] = a4.y;
            As[nb][(ac+2)*128 + ar] = a4.z;
            As[nb][(ac+3)*128 + ar] = a4.w;
            *(float4*)&Bs[nb][br*128 + bc] = b4;
            __syncthreads();
            cur = nb;
        }
    }
    int row0 = bm + ty*8, col0 = bn + tx*8;
    float4 bs0 = *(const float4*)&bias[col0];
    float4 bs1 = *(const float4*)&bias[col0+4];
    #pragma unroll
    for (int i = 0; i < 8; i++) {
        float4 v0 = {acc[i][0]+bs0.x, acc[i][1]+bs0.y, acc[i][2]+bs0.z, acc[i][3]+bs0.w};
        float4 v1 = {acc[i][4]+bs1.x, acc[i][5]+bs1.y, acc[i][6]+bs1.z, acc[i][7]+bs1.w};
        if (ACT) {
            v0.x=gelu_exact(v0.x); v0.y=gelu_exact(v0.y); v0.z=gelu_exact(v0.z); v0.w=gelu_exact(v0.w);
            v1.x=gelu_exact(v1.x); v1.y=gelu_exact(v1.y); v1.z=gelu_exact(v1.z); v1.w=gelu_exact(v1.w);
        }
        *(float4*)&C[(size_t)(row0+i)*N + col0]     = v0;
        *(float4*)&C[(size_t)(row0+i)*N + col0 + 4] = v1;
    }
}

__global__ __launch_bounds__(256) void ln_kernel(
    const float* __restrict__ gamma, const float* __restrict__ beta)
{
    __shared__ float red[8];
    int row = blockIdx.x, tid = threadIdx.x, lane = tid & 31, wid = tid >> 5;
    size_t base = (size_t)row * DD;
    float y0 = g_gath[base+tid]     + g_ffn[base+tid];
    float y1 = g_gath[base+tid+256] + g_ffn[base+tid+256];
    float s = y0 + y1;
    #pragma unroll
    for (int off = 16; off; off >>= 1) s += __shfl_xor_sync(0xffffffffu, s, off);
    if (lane == 0) red[wid] = s;
    __syncthreads();
    float mean = (red[0]+red[1]+red[2]+red[3]+red[4]+red[5]+red[6]+red[7]) * (1.0f/DD);
    __syncthreads();
    float d0 = y0 - mean, d1 = y1 - mean;
    float q = d0*d0 + d1*d1;
    #pragma unroll
    for (int off = 16; off; off >>= 1) q += __shfl_xor_sync(0xffffffffu, q, off);
    if (lane == 0) red[wid] = q;
    __syncthreads();
    float inv = rsqrtf((red[0]+red[1]+red[2]+red[3]+red[4]+red[5]+red[6]+red[7])*(1.0f/DD) + 1e-5f);
    g_y[base+tid]     = d0*inv*gamma[tid]     + beta[tid];
    g_y[base+tid+256] = d1*inv*gamma[tid+256] + beta[tid+256];
}

// One-hop grid barrier: CTA release-stores its padded flag; 64 threads poll 2 flags each.
__device__ __forceinline__ void gridbar(unsigned ph) {
    __syncthreads();
    if (threadIdx.x == 0) st_rel(&g_arr[blockIdx.x*32], ph);
    if (threadIdx.x < 64) {
        while (ld_acq(&g_arr[(threadIdx.x*2)*32]) < ph) {}
        while (ld_acq(&g_arr[(threadIdx.x*2+1)*32]) < ph) {}
    }
    __syncthreads();
}

// dynamic smem layout (floats):
#define OFF_W1T  0                      // 8*DP    : Wt1 mem-half slice [jj][d]
#define OFF_W2T  (OFF_W1T + 8*DP)       // 32*HP   : Wt2 slice [oo][j]
#define OFF_MEMS (OFF_W2T + 32*HP)      // 8*DP    : staged mem_t
#define OFF_HS   (OFF_MEMS + 8*DP)      // HP      : staged h_t[bPh]
#define OFF_REDA (OFF_HS + HP)          // 8*64    : phase-A partials
#define SCAN_SMEM_FLOATS (OFF_REDA + 8*64)

__global__ __launch_bounds__(256) void scan_kernel(
    const float* __restrict__ Wt1, const float* __restrict__ Wt2,
    const float* __restrict__ bt2)
{
    extern __shared__ float sm[];
    float* w1T  = sm + OFF_W1T;
    float* w2T  = sm + OFF_W2T;
    float* memS = sm + OFF_MEMS;
    float* hS   = sm + OFF_HS;
    float* redA = sm + OFF_REDA;

    int tid = threadIdx.x, lane = tid & 31, w = tid >> 5;
    int jc0 = blockIdx.x * 8;                 // phase A j-slice
    int bPh = blockIdx.x >> 4;                // phase B batch
    int oc0 = (blockIdx.x & 15) << 5;         // phase B o-slice (32 cols)

    for (int i = tid; i < 8*DD; i += 256) {
        int jj = i >> 9, d = i & (DD-1);
        w1T[jj*DP + d] = Wt1[(size_t)(DD + d)*HID + jc0 + jj];
    }
    for (int i = tid; i < 32*HID; i += 256) {
        int j = i >> 5, oo = i & 31;
        w2T[oo*HP + j] = Wt2[(size_t)j*DD + oc0 + oo];
    }
    __syncthreads();
    float b2r = (lane < 4) ? __ldg(&bt2[oc0 + (w<<2) + lane]) : 0.f;

    int bA = lane >> 2, j0 = (lane & 3) << 1;   // phase A lane mapping

    unsigned ph = 1;
    for (int t = 0; t < TT; t++) {
        // prefetch P for this CTA's 64 (b, j) outputs before the barrier
        float pv = 0.f;
        if (tid < 64) pv = __ldg(&g_big[((size_t)(tid>>3)*TT + t)*HID + jc0 + (tid&7)]);

        gridbar(ph++);                    // mem_t globally visible
        #pragma unroll
        for (int i = 0; i < 4; i++) {     // stage mem [8][512] -> memS
            int idx = tid + 256*i;
            float4 v = __ldcg((const float4*)g_mem + idx);
            *((float4*)&memS[(idx >> 7) * DP] + (idx & 127)) = v;
        }
        __syncthreads();
        {   // phase A: warp w covers d in [64w,64w+64); lane -> (bA, j0/j0+1)
            float a0 = 0.f, a1 = 0.f;
            const float4* mp  = (const float4*)&memS[bA*DP + 64*w];
            const float4* w0p = (const float4*)&w1T[j0*DP + 64*w];
            const float4* w1p = (const float4*)&w1T[(j0+1)*DP + 64*w];
            #pragma unroll
            for (int i = 0; i < 16; i++) {
                float4 m4 = mp[i], u4 = w0p[i], v4 = w1p[i];
                a0 += m4.x*u4.x + m4.y*u4.y + m4.z*u4.z + m4.w*u4.w;
                a1 += m4.x*v4.x + m4.y*v4.y + m4.z*v4.z + m4.w*v4.w;
            }
            *(float2*)&redA[w*64 + bA*8 + j0] = make_float2(a0, a1);
        }
        __syncthreads();
        if (tid < 64) {
            float s = pv;
            #pragma unroll
            for (int k = 0; k < 8; k++) s += redA[k*64 + tid];
            __stcg(&g_hbuf[(tid>>3)*HID + jc0 + (tid&7)], gelu_exact(s));
        }

        gridbar(ph++);                    // h_t globally visible
        // stage h[bPh] (4KB): one float4 per thread
        ((float4*)hS)[tid] = __ldcg((const float4*)(g_hbuf + (size_t)bPh*HID) + tid);
        __syncthreads();
        {   // phase B: warp w owns o = oc0 + 4w .. +3; lanes split j (32 j each)
            float acc0=0.f, acc1=0.f, acc2=0.f, acc3=0.f;
            const float4* hp  = (const float4*)hS;
            const float4* q0p = (const float4*)&w2T[(w*4+0)*HP];
            const float4* q1p = (const float4*)&w2T[(w*4+1)*HP];
            const float4* q2p = (const float4*)&w2T[(w*4+2)*HP];
            const float4* q3p = (const float4*)&w2T[(w*4+3)*HP];
            #pragma unroll
            for (int i = 0; i < 8; i++) {
                int idx = i*32 + lane;
                float4 h4 = hp[idx];
                float4 q0 = q0p[idx], q1 = q1p[idx], q2 = q2p[idx], q3 = q3p[idx];
                acc0 += h4.x*q0.x + h4.y*q0.y + h4.z*q0.z + h4.w*q0.w;
                acc1 += h4.x*q1.x + h4.y*q1.y + h4.z*q1.z + h4.w*q1.w;
                acc2 += h4.x*q2.x + h4.y*q2.y + h4.z*q2.z + h4.w*q2.w;
                acc3 += h4.x*q3.x + h4.y*q3.y + h4.z*q3.z + h4.w*q3.w;
            }
            #pragma unroll
            for (int off = 16; off; off >>= 1) {
                acc0 += __shfl_xor_sync(0xffffffffu, acc0, off);
                acc1 += __shfl_xor_sync(0xffffffffu, acc1, off);
                acc2 += __shfl_xor_sync(0xffffffffu, acc2, off);
                acc3 += __shfl_xor_sync(0xffffffffu, acc3, off);
            }
            if (lane < 4) {
                float p = (lane==0)?acc0:(lane==1)?acc1:(lane==2)?acc2:acc3;
                p += b2r;
                int o = oc0 + (w<<2) + lane;
                float mo = memS[bPh*DP + o];
                float gg = 1.0f / (1.0f + __expf(-p));
                __stcg(&g_mem[(size_t)bPh*DD + o], mo + gg*(p - mo));
            }
        }
    }
}

__global__ __launch_bounds__(256) void out_kernel(
    const float* __restrict__ Wo, const float* __restrict__ bo, float* __restrict__ out)
{
    int gid = blockIdx.x*256 + threadIdx.x;
    int b = gid >> 9, o = gid & (DD-1);
    float s = bo[o];
    const float* m = &g_mem[(size_t)b*DD];
    #pragma unroll 8
    for (int d = 0; d < DD; d++) s += m[d] * Wo[(size_t)d*DD + o];
    out[gid] = s;
}

extern "C" void kernel_launch(void* const* d_in, const int* in_sizes, int n_in,
                              void* d_out, int out_size)
{
    const float* x    = (const float*)d_in[0];
    const float* Wq   = (const float*)d_in[1];
    const float* bq   = (const float*)d_in[2];
    const float* Wk   = (const float*)d_in[3];
    const float* bk   = (const float*)d_in[4];
    const float* W1   = (const float*)d_in[5];
    const float* b1   = (const float*)d_in[6];
    const float* W2   = (const float*)d_in[7];
    const float* b2   = (const float*)d_in[8];
    const float* ln_g = (const float*)d_in[9];
    const float* ln_b = (const float*)d_in[10];
    const float* Wt1  = (const float*)d_in[11];
    const float* bt1  = (const float*)d_in[12];
    const float* Wt2  = (const float*)d_in[13];
    const float* bt2  = (const float*)d_in[14];
    const float* Wo   = (const float*)d_in[15];
    const float* bo   = (const float*)d_in[16];
    float* out = (float*)d_out;

    static bool attr_done = false;
    if (!attr_done) {
        cudaFuncSetAttribute(scan_kernel, cudaFuncAttributeMaxDynamicSharedMemorySize,
                             SCAN_SMEM_FLOATS * (int)sizeof(float));
        attr_done = true;
    }

    init_kernel<<<16, 256>>>();
    qk_kernel<<<BT/4, 128>>>(x, Wq, bq, Wk, bk);
    sim_topk_kernel<<<BB*(TT/8), 256>>>();
    gather_kernel<<<BT, 128>>>(x);
    {   // GEMM1: [BT,512] @ W1[512,1024] -> gelu -> g_big
        dim3 g(HID/128, BT/128);
        sgemm128<1,0><<<g, 256>>>(W1, b1, HID, DD);
    }
    {   // GEMM2: [BT,1024] @ W2[1024,512] -> g_ffn
        dim3 g(DD/128, BT/128);
        sgemm128<0,1><<<g, 256>>>(W2, b2, DD, HID);
    }
    ln_kernel<<<BT, 256>>>(ln_g, ln_b);
    {   // P-GEMM: g_y[BT,512] @ Wt1[0:512,1024] + bt1 -> g_big
        dim3 g(HID/128, BT/128);
        sgemm128<0,2><<<g, 256>>>(Wt1, bt1, HID, DD);
    }
    scan_kernel<<<NCTA, 256, SCAN_SMEM_FLOATS * (int)sizeof(float)>>>(Wt1, Wt2, bt2);
    out_kernel<<<(BB*DD)/256, 256>>>(Wo, bo, out);
}

// round 9
// speedup vs baseline: 1.0222x; 1.0222x over previous
#include <cuda_runtime.h>
#include <cfloat>

#define BB 8
#define TT 2048
#define DD 512
#define KQ 32
#define TOPK 4
#define BT (BB*TT)
#define HID 1024
#define NCTA 128
#define DP (DD+4)
#define HP (HID+4)

__device__ float g_q[BT*KQ];
__device__ float g_kk[BT*KQ];
__device__ int   g_idx[BT*TOPK];
__device__ float g_gath[BT*DD];
__device__ float g_big[BT*HID];   // GEMM1 hidden, later reused for P
__device__ float g_ffn[BT*DD];
__device__ float g_y[BT*DD];
__device__ float g_hbuf[BB*HID];
__device__ float g_mem[BB*DD];
__device__ unsigned g_count;      // barrier arrival counter (monotonic per replay)
__device__ unsigned g_go;         // barrier broadcast word

__device__ __forceinline__ float gelu_exact(float v) {
    return 0.5f * v * (1.0f + erff(v * 0.70710678118654752440f));
}
__device__ __forceinline__ unsigned ld_acq(const unsigned* p) {
    unsigned v; asm volatile("ld.acquire.gpu.u32 %0, [%1];" : "=r"(v) : "l"(p)); return v;
}
__device__ __forceinline__ void st_rel(unsigned* p, unsigned v) {
    asm volatile("st.release.gpu.u32 [%0], %1;" :: "l"(p), "r"(v));
}
__device__ __forceinline__ unsigned atom_inc_acqrel(unsigned* p) {
    unsigned old;
    asm volatile("atom.add.acq_rel.gpu.global.u32 %0, [%1], %2;"
                 : "=r"(old) : "l"(p), "r"(1u));
    return old;
}

__global__ void init_kernel() {
    int t = blockIdx.x * blockDim.x + threadIdx.x;
    if (t < BB*DD) g_mem[t] = 0.0f;
    if (t == 0) { g_count = 0u; g_go = 0u; }
}

__global__ __launch_bounds__(128) void qk_kernel(
    const float* __restrict__ x, const float* __restrict__ Wq, const float* __restrict__ bq,
    const float* __restrict__ Wk, const float* __restrict__ bk)
{
    __shared__ float xs[4*DD];
    int r0 = blockIdx.x * 4, tid = threadIdx.x;
    for (int i = tid; i < 4*DD; i += 128) xs[i] = x[(size_t)r0*DD + i];
    __syncthreads();
    int r = tid >> 5, j = tid & 31;
    float sq = 0.f, sk = 0.f;
    const float* xr = &xs[r*DD];
    #pragma unroll 8
    for (int d = 0; d < DD; d++) {
        float xv = xr[d];
        sq += xv * Wq[d*KQ + j];
        sk += xv * Wk[d*KQ + j];
    }
    g_q [(size_t)(r0+r)*KQ + j] = sq + bq[j];
    g_kk[(size_t)(r0+r)*KQ + j] = sk + bk[j];
}

__global__ __launch_bounds__(256) void sim_topk_kernel() {
    __shared__ float ks[256*33];
    int b = blockIdx.x >> 8, t0 = (blockIdx.x & 255) * 8;
    int tid = threadIdx.x, warp = tid >> 5, lane = tid & 31;
    int t = t0 + warp;
    float qreg[KQ];
    #pragma unroll
    for (int i = 0; i < KQ; i++) qreg[i] = g_q[((size_t)b*TT + t)*KQ + i];
    float v0=-FLT_MAX,v1=-FLT_MAX,v2=-FLT_MAX,v3=-FLT_MAX;
    int   i0=0x7fffffff,i1=0x7fffffff,i2=0x7fffffff,i3=0x7fffffff;
    for (int c = 0; c < 8; c++) {
        int s0 = c * 256;
        __syncthreads();
        for (int i = tid; i < 256*KQ; i += 256) {
            int sl = i >> 5, kv = i & 31;
            ks[sl*33 + kv] = g_kk[((size_t)b*TT + s0 + sl)*KQ + kv];
        }
        __syncthreads();
        #pragma unroll
        for (int it = 0; it < 8; it++) {
            int sl = (it << 5) + lane;
            const float* kr = &ks[sl*33];
            float sim = 0.f;
            #pragma unroll
            for (int i = 0; i < KQ; i++) sim += qreg[i]*kr[i];
            int s = s0 + sl;
            if (sim > v3) {
                if (sim > v1) {
                    v3=v2;i3=i2; v2=v1;i2=i1;
                    if (sim > v0) { v1=v0;i1=i0; v0=sim;i0=s; }
                    else          { v1=sim;i1=s; }
                } else {
                    if (sim > v2) { v3=v2;i3=i2; v2=sim;i2=s; }
                    else          { v3=sim;i3=s; }
                }
            }
        }
    }
    for (int r = 0; r < 4; r++) {
        float bv = v0; int bi = i0;
        #pragma unroll
        for (int off = 16; off; off >>= 1) {
            float ov = __shfl_xor_sync(0xffffffffu, bv, off);
            int   oi = __shfl_xor_sync(0xffffffffu, bi, off);
            if (ov > bv || (ov == bv && oi < bi)) { bv = ov; bi = oi; }
        }
        if (i0 == bi) { v0=v1;i0=i1; v1=v2;i1=i2; v2=v3;i2=i3; v3=-FLT_MAX;i3=0x7fffffff; }
        if (lane == 0) g_idx[((size_t)b*TT + t)*TOPK + r] = bi;
    }
}

__global__ __launch_bounds__(128) void gather_kernel(const float* __restrict__ x) {
    int bt = blockIdx.x, b = bt >> 11;
    const int4 iv = *(const int4*)&g_idx[(size_t)bt*TOPK];
    const float4* xb = (const float4*)(x + (size_t)b*TT*DD);
    int d = threadIdx.x;
    float4 a = xb[(size_t)iv.x*(DD/4)+d], b4 = xb[(size_t)iv.y*(DD/4)+d];
    float4 c = xb[(size_t)iv.z*(DD/4)+d], e  = xb[(size_t)iv.w*(DD/4)+d];
    float4 m = {0.25f*(a.x+b4.x+c.x+e.x), 0.25f*(a.y+b4.y+c.y+e.y),
                0.25f*(a.z+b4.z+c.z+e.z), 0.25f*(a.w+b4.w+c.w+e.w)};
    ((float4*)(g_gath + (size_t)bt*DD))[d] = m;
}

// 128x128 tile, 8x8 micro, double-buffered. C = act(A @ B + bias).
// MODE 0: g_gath->g_big(gelu); 1: g_big->g_ffn; 2: g_y->g_big
template<int ACT, int MODE>
__global__ __launch_bounds__(256) void sgemm128(
    const float* __restrict__ Bmat, const float* __restrict__ bias, int N, int K)
{
    const float* A = (MODE==0) ? g_gath : (MODE==1) ? g_big : g_y;
    float*       C = (MODE==1) ? g_ffn  : g_big;
    __shared__ float As[2][8*128];
    __shared__ float Bs[2][8*128];
    int tid = threadIdx.x;
    int bm = blockIdx.y * 128, bn = blockIdx.x * 128;
    int tx = tid & 15, ty = tid >> 4;
    int ar = tid >> 1, ac = (tid & 1) << 2;
    int br = tid >> 5, bc = (tid & 31) << 2;
    const float* Ap = A + (size_t)(bm + ar)*K + ac;
    const float* Bp = Bmat + (size_t)br*N + bn + bc;
    float acc[8][8] = {};
    {
        float4 a4 = *(const float4*)Ap;
        float4 b4 = *(const float4*)Bp;
        As[0][(ac+0)*128 + ar] = a4.x;
        As[0][(ac+1)*128 + ar] = a4.y;
        As[0][(ac+2)*128 + ar] = a4.z;
        As[0][(ac+3)*128 + ar] = a4.w;
        *(float4*)&Bs[0][br*128 + bc] = b4;
    }
    __syncthreads();
    int cur = 0;
    for (int k0 = 0; k0 < K; k0 += 8) {
        float4 a4, b4;
        bool more = (k0 + 8) < K;
        if (more) {
            a4 = *(const float4*)(Ap + k0 + 8);
            b4 = *(const float4*)(Bp + (size_t)(k0 + 8)*N);
        }
        #pragma unroll
        for (int kk = 0; kk < 8; kk++) {
            float4 a0 = *(const float4*)&As[cur][kk*128 + ty*8];
            float4 a1 = *(const float4*)&As[cur][kk*128 + ty*8 + 4];
            float4 b0 = *(const float4*)&Bs[cur][kk*128 + tx*8];
            float4 b1 = *(const float4*)&Bs[cur][kk*128 + tx*8 + 4];
            float av[8] = {a0.x,a0.y,a0.z,a0.w,a1.x,a1.y,a1.z,a1.w};
            float bv[8] = {b0.x,b0.y,b0.z,b0.w,b1.x,b1.y,b1.z,b1.w};
            #pragma unroll
            for (int i = 0; i < 8; i++)
                #pragma unroll
                for (int j = 0; j < 8; j++) acc[i][j] += av[i]*bv[j];
        }
        if (more) {
            int nb = cur ^ 1;
            As[nb][(ac+0)*128 + ar] = a4.x;
            As[nb][(ac+1)*128 + ar] = a4.y;
            As[nb][(ac+2)*128 + ar] = a4.z;
            As[nb][(ac+3)*128 + ar] = a4.w;
            *(float4*)&Bs[nb][br*128 + bc] = b4;
            __syncthreads();
            cur = nb;
        }
    }
    int row0 = bm + ty*8, col0 = bn + tx*8;
    float4 bs0 = *(const float4*)&bias[col0];
    float4 bs1 = *(const float4*)&bias[col0+4];
    #pragma unroll
    for (int i = 0; i < 8; i++) {
        float4 v0 = {acc[i][0]+bs0.x, acc[i][1]+bs0.y, acc[i][2]+bs0.z, acc[i][3]+bs0.w};
        float4 v1 = {acc[i][4]+bs1.x, acc[i][5]+bs1.y, acc[i][6]+bs1.z, acc[i][7]+bs1.w};
        if (ACT) {
            v0.x=gelu_exact(v0.x); v0.y=gelu_exact(v0.y); v0.z=gelu_exact(v0.z); v0.w=gelu_exact(v0.w);
            v1.x=gelu_exact(v1.x); v1.y=gelu_exact(v1.y); v1.z=gelu_exact(v1.z); v1.w=gelu_exact(v1.w);
        }
        *(float4*)&C[(size_t)(row0+i)*N + col0]     = v0;
        *(float4*)&C[(size_t)(row0+i)*N + col0 + 4] = v1;
    }
}

__global__ __launch_bounds__(256) void ln_kernel(
    const float* __restrict__ gamma, const float* __restrict__ beta)
{
    __shared__ float red[8];
    int row = blockIdx.x, tid = threadIdx.x, lane = tid & 31, wid = tid >> 5;
    size_t base = (size_t)row * DD;
    float y0 = g_gath[base+tid]     + g_ffn[base+tid];
    float y1 = g_gath[base+tid+256] + g_ffn[base+tid+256];
    float s = y0 + y1;
    #pragma unroll
    for (int off = 16; off; off >>= 1) s += __shfl_xor_sync(0xffffffffu, s, off);
    if (lane == 0) red[wid] = s;
    __syncthreads();
    float mean = (red[0]+red[1]+red[2]+red[3]+red[4]+red[5]+red[6]+red[7]) * (1.0f/DD);
    __syncthreads();
    float d0 = y0 - mean, d1 = y1 - mean;
    float q = d0*d0 + d1*d1;
    #pragma unroll
    for (int off = 16; off; off >>= 1) q += __shfl_xor_sync(0xffffffffu, q, off);
    if (lane == 0) red[wid] = q;
    __syncthreads();
    float inv = rsqrtf((red[0]+red[1]+red[2]+red[3]+red[4]+red[5]+red[6]+red[7])*(1.0f/DD) + 1e-5f);
    g_y[base+tid]     = d0*inv*gamma[tid]     + beta[tid];
    g_y[base+tid+256] = d1*inv*gamma[tid+256] + beta[tid+256];
}

// Atomic-counter grid barrier with last-arriver broadcast.
// Thread 0 per CTA: acq_rel atomicAdd on one counter; the CTA observing
// old == ph*NCTA-1 is last and release-stores g_go; others spin-acquire g_go.
__device__ __forceinline__ void gridbar(unsigned ph) {
    __syncthreads();
    if (threadIdx.x == 0) {
        unsigned old = atom_inc_acqrel(&g_count);
        if (old == ph*NCTA - 1u) {
            st_rel(&g_go, ph);
        } else {
            while (ld_acq(&g_go) < ph) {}
        }
    }
    __syncthreads();
}

// dynamic smem layout (floats):
#define OFF_W1T  0                      // 8*DP    : Wt1 mem-half slice [jj][d]
#define OFF_W2T  (OFF_W1T + 8*DP)       // 32*HP   : Wt2 slice [oo][j]
#define OFF_MEMS (OFF_W2T + 32*HP)      // 8*DP    : staged mem_t
#define OFF_HS   (OFF_MEMS + 8*DP)      // HP      : staged h_t[bPh]
#define OFF_REDA (OFF_HS + HP)          // 8*64    : phase-A partials
#define SCAN_SMEM_FLOATS (OFF_REDA + 8*64)

__global__ __launch_bounds__(256) void scan_kernel(
    const float* __restrict__ Wt1, const float* __restrict__ Wt2,
    const float* __restrict__ bt2)
{
    extern __shared__ float sm[];
    float* w1T  = sm + OFF_W1T;
    float* w2T  = sm + OFF_W2T;
    float* memS = sm + OFF_MEMS;
    float* hS   = sm + OFF_HS;
    float* redA = sm + OFF_REDA;

    int tid = threadIdx.x, lane = tid & 31, w = tid >> 5;
    int jc0 = blockIdx.x * 8;                 // phase A j-slice
    int bPh = blockIdx.x >> 4;                // phase B batch
    int oc0 = (blockIdx.x & 15) << 5;         // phase B o-slice (32 cols)

    for (int i = tid; i < 8*DD; i += 256) {
        int jj = i >> 9, d = i & (DD-1);
        w1T[jj*DP + d] = Wt1[(size_t)(DD + d)*HID + jc0 + jj];
    }
    for (int i = tid; i < 32*HID; i += 256) {
        int j = i >> 5, oo = i & 31;
        w2T[oo*HP + j] = Wt2[(size_t)j*DD + oc0 + oo];
    }
    __syncthreads();
    float b2r = (lane < 4) ? __ldg(&bt2[oc0 + (w<<2) + lane]) : 0.f;

    int bA = lane >> 2, j0 = (lane & 3) << 1;   // phase A lane mapping

    unsigned ph = 1;
    for (int t = 0; t < TT; t++) {
        // prefetch P for this CTA's 64 (b, j) outputs before the barrier
        float pv = 0.f;
        if (tid < 64) pv = __ldg(&g_big[((size_t)(tid>>3)*TT + t)*HID + jc0 + (tid&7)]);

        gridbar(ph++);                    // mem_t globally visible
        #pragma unroll
        for (int i = 0; i < 4; i++) {     // stage mem [8][512] -> memS
            int idx = tid + 256*i;
            float4 v = __ldcg((const float4*)g_mem + idx);
            *((float4*)&memS[(idx >> 7) * DP] + (idx & 127)) = v;
        }
        __syncthreads();
        {   // phase A: warp w covers d in [64w,64w+64); lane -> (bA, j0/j0+1)
            float a0 = 0.f, a1 = 0.f;
            const float4* mp  = (const float4*)&memS[bA*DP + 64*w];
            const float4* w0p = (const float4*)&w1T[j0*DP + 64*w];
            const float4* w1p = (const float4*)&w1T[(j0+1)*DP + 64*w];
            #pragma unroll
            for (int i = 0; i < 16; i++) {
                float4 m4 = mp[i], u4 = w0p[i], v4 = w1p[i];
                a0 += m4.x*u4.x + m4.y*u4.y + m4.z*u4.z + m4.w*u4.w;
                a1 += m4.x*v4.x + m4.y*v4.y + m4.z*v4.z + m4.w*v4.w;
            }
            *(float2*)&redA[w*64 + bA*8 + j0] = make_float2(a0, a1);
        }
        __syncthreads();
        if (tid < 64) {
            float s = pv;
            #pragma unroll
            for (int k = 0; k < 8; k++) s += redA[k*64 + tid];
            __stcg(&g_hbuf[(tid>>3)*HID + jc0 + (tid&7)], gelu_exact(s));
        }

        gridbar(ph++);                    // h_t globally visible
        // stage h[bPh] (4KB): one float4 per thread
        ((float4*)hS)[tid] = __ldcg((const float4*)(g_hbuf + (size_t)bPh*HID) + tid);
        __syncthreads();
        {   // phase B: warp w owns o = oc0 + 4w .. +3; lanes split j (32 j each)
            float acc0=0.f, acc1=0.f, acc2=0.f, acc3=0.f;
            const float4* hp  = (const float4*)hS;
            const float4* q0p = (const float4*)&w2T[(w*4+0)*HP];
            const float4* q1p = (const float4*)&w2T[(w*4+1)*HP];
            const float4* q2p = (const float4*)&w2T[(w*4+2)*HP];
            const float4* q3p = (const float4*)&w2T[(w*4+3)*HP];
            #pragma unroll
            for (int i = 0; i < 8; i++) {
                int idx = i*32 + lane;
                float4 h4 = hp[idx];
                float4 q0 = q0p[idx], q1 = q1p[idx], q2 = q2p[idx], q3 = q3p[idx];
                acc0 += h4.x*q0.x + h4.y*q0.y + h4.z*q0.z + h4.w*q0.w;
                acc1 += h4.x*q1.x + h4.y*q1.y + h4.z*q1.z + h4.w*q1.w;
                acc2 += h4.x*q2.x + h4.y*q2.y + h4.z*q2.z + h4.w*q2.w;
                acc3 += h4.x*q3.x + h4.y*q3.y + h4.z*q3.z + h4.w*q3.w;
            }
            #pragma unroll
            for (int off = 16; off; off >>= 1) {
                acc0 += __shfl_xor_sync(0xffffffffu, acc0, off);
                acc1 += __shfl_xor_sync(0xffffffffu, acc1, off);
                acc2 += __shfl_xor_sync(0xffffffffu, acc2, off);
                acc3 += __shfl_xor_sync(0xffffffffu, acc3, off);
            }
            if (lane < 4) {
                float p = (lane==0)?acc0:(lane==1)?acc1:(lane==2)?acc2:acc3;
                p += b2r;
                int o = oc0 + (w<<2) + lane;
                float mo = memS[bPh*DP + o];
                float gg = 1.0f / (1.0f + __expf(-p));
                __stcg(&g_mem[(size_t)bPh*DD + o], mo + gg*(p - mo));
            }
        }
    }
}

__global__ __launch_bounds__(256) void out_kernel(
    const float* __restrict__ Wo, const float* __restrict__ bo, float* __restrict__ out)
{
    int gid = blockIdx.x*256 + threadIdx.x;
    int b = gid >> 9, o = gid & (DD-1);
    float s = bo[o];
    const float* m = &g_mem[(size_t)b*DD];
    #pragma unroll 8
    for (int d = 0; d < DD; d++) s += m[d] * Wo[(size_t)d*DD + o];
    out[gid] = s;
}

extern "C" void kernel_launch(void* const* d_in, const int* in_sizes, int n_in,
                              void* d_out, int out_size)
{
    const float* x    = (const float*)d_in[0];
    const float* Wq   = (const float*)d_in[1];
    const float* bq   = (const float*)d_in[2];
    const float* Wk   = (const float*)d_in[3];
    const float* bk   = (const float*)d_in[4];
    const float* W1   = (const float*)d_in[5];
    const float* b1   = (const float*)d_in[6];
    const float* W2   = (const float*)d_in[7];
    const float* b2   = (const float*)d_in[8];
    const float* ln_g = (const float*)d_in[9];
    const float* ln_b = (const float*)d_in[10];
    const float* Wt1  = (const float*)d_in[11];
    const float* bt1  = (const float*)d_in[12];
    const float* Wt2  = (const float*)d_in[13];
    const float* bt2  = (const float*)d_in[14];
    const float* Wo   = (const float*)d_in[15];
    const float* bo   = (const float*)d_in[16];
    float* out = (float*)d_out;

    static bool attr_done = false;
    if (!attr_done) {
        cudaFuncSetAttribute(scan_kernel, cudaFuncAttributeMaxDynamicSharedMemorySize,
                             SCAN_SMEM_FLOATS * (int)sizeof(float));
        attr_done = true;
    }

    init_kernel<<<16, 256>>>();
    qk_kernel<<<BT/4, 128>>>(x, Wq, bq, Wk, bk);
    sim_topk_kernel<<<BB*(TT/8), 256>>>();
    gather_kernel<<<BT, 128>>>(x);
    {   // GEMM1: [BT,512] @ W1[512,1024] -> gelu -> g_big
        dim3 g(HID/128, BT/128);
        sgemm128<1,0><<<g, 256>>>(W1, b1, HID, DD);
    }
    {   // GEMM2: [BT,1024] @ W2[1024,512] -> g_ffn
        dim3 g(DD/128, BT/128);
        sgemm128<0,1><<<g, 256>>>(W2, b2, DD, HID);
    }
    ln_kernel<<<BT, 256>>>(ln_g, ln_b);
    {   // P-GEMM: g_y[BT,512] @ Wt1[0:512,1024] + bt1 -> g_big
        dim3 g(HID/128, BT/128);
        sgemm128<0,2><<<g, 256>>>(Wt1, bt1, HID, DD);
    }
    scan_kernel<<<NCTA, 256, SCAN_SMEM_FLOATS * (int)sizeof(float)>>>(Wt1, Wt2, bt2);
    out_kernel<<<(BB*DD)/256, 256>>>(Wo, bo, out);
}